// round 9
// baseline (speedup 1.0000x reference)
#include <cuda_runtime.h>
#include <cuda_fp16.h>
#include <math.h>
#include <stdint.h>

// Problem constants
#define BB 8
#define FF 16
#define NN 2048
#define JS 4
#define NCOLS 21
#define OUT_ELEMS (BB*FF*NCOLS)
#define NW2 1024                 // uint32 (fp16-pair) words per row
#define NH2 1024                 // uint16 (fp8-pair) words per row

// scales: psi pre-scaled by 2^5; corrections scaled by 2^12
#define PS    32.0f
#define CS    4096.0f
#define S_MAIN (1.0f/32.0f)
#define S_CORR (1.0f/(32.0f*4096.0f))

// ---------------- scratch ----------------
__device__ __align__(256) uint32_t g_X2h[BB*FF*NW2];
__device__ __align__(256) uint16_t g_X8[BB*FF*NH2],  g_X8l[BB*FF*NH2];
__device__ __align__(256) uint32_t g_P2h[(size_t)JS*NN*NW2];
__device__ __align__(256) uint16_t g_P8[(size_t)JS*NN*NH2], g_P8l[(size_t)JS*NN*NH2];
__device__ __align__(256) uint32_t g_S2h[(size_t)BB*JS*FF*NW2];
__device__ __align__(256) uint16_t g_S8[(size_t)BB*JS*FF*NH2], g_S8l[(size_t)BB*JS*FF*NH2];

// ---------------- helpers ----------------
__device__ __forceinline__ uint32_t smem_u32(const void* p) {
    uint32_t a;
    asm("{ .reg .u64 t; cvta.to.shared.u64 t, %1; cvt.u32.u64 %0, t; }" : "=r"(a) : "l"(p));
    return a;
}
__device__ __forceinline__ void cp16(uint32_t s, const void* g) {
    asm volatile("cp.async.cg.shared.global [%0], [%1], 16;\n" :: "r"(s), "l"(g));
}
__device__ __forceinline__ uint32_t pack2(float a, float b) {
    __half2 h = __floats2half2_rn(a, b);
    return *reinterpret_cast<uint32_t*>(&h);
}
__device__ __forceinline__ uint16_t pack_e4m3(float lo, float hi) {
    uint16_t u;
    asm("cvt.rn.satfinite.e4m3x2.f32 %0, %1, %2;" : "=h"(u) : "f"(hi), "f"(lo));
    return u;
}
#define MMA_F16(C, A, B0, B1)                                                 \
    asm volatile(                                                             \
        "mma.sync.aligned.m16n8k16.row.col.f32.f16.f16.f32 "                  \
        "{%0,%1,%2,%3}, {%4,%5,%6,%7}, {%8,%9}, {%0,%1,%2,%3};\n"             \
        : "+f"((C)[0]), "+f"((C)[1]), "+f"((C)[2]), "+f"((C)[3])              \
        : "r"((A)[0]), "r"((A)[1]), "r"((A)[2]), "r"((A)[3]), "r"(B0), "r"(B1))
#define MMA_E4M3(C, A, B0, B1)                                                \
    asm volatile(                                                             \
        "mma.sync.aligned.m16n8k32.row.col.f32.e4m3.e4m3.f32 "                \
        "{%0,%1,%2,%3}, {%4,%5,%6,%7}, {%8,%9}, {%0,%1,%2,%3};\n"             \
        : "+f"((C)[0]), "+f"((C)[1]), "+f"((C)[2]), "+f"((C)[3])              \
        : "r"((A)[0]), "r"((A)[1]), "r"((A)[2]), "r"((A)[3]), "r"(B0), "r"(B1))
#define LDSM4(R, addr)                                                        \
    asm volatile("ldmatrix.sync.aligned.m8n8.x4.shared.b16 {%0,%1,%2,%3}, [%4];" \
        : "=r"((R)[0]), "=r"((R)[1]), "=r"((R)[2]), "=r"((R)[3]) : "r"(addr))

// ---------------- small kernels ----------------
__global__ void zero_phi_kernel(float* __restrict__ out) {
    int i = blockIdx.x * blockDim.x + threadIdx.x;
    if (i < OUT_ELEMS) out[i] = 0.0f;
}

__global__ void phi0_kernel(const float* __restrict__ x, const float* __restrict__ lp,
                            float* __restrict__ out) {
    int r = blockIdx.x;
    const float* xr = x + (size_t)r * NN;
    float s = 0.0f;
    for (int n = threadIdx.x; n < NN; n += 256) s += xr[n] * lp[n];
    __shared__ float red[8];
    #pragma unroll
    for (int o = 16; o; o >>= 1) s += __shfl_xor_sync(0xffffffffu, s, o);
    if ((threadIdx.x & 31) == 0) red[threadIdx.x >> 5] = s;
    __syncthreads();
    if (threadIdx.x < 8) {
        s = red[threadIdx.x];
        #pragma unroll
        for (int o = 4; o; o >>= 1) s += __shfl_xor_sync(0xffu, s, o);
        if (threadIdx.x == 0) out[r * NCOLS + 0] = s;
    }
}

__global__ void split_pack_x(const float* __restrict__ x) {
    int i = blockIdx.x * blockDim.x + threadIdx.x;
    if (i < BB * FF * NW2) {
        float a = x[2 * i], b = x[2 * i + 1];
        float ah = __half2float(__float2half_rn(a));
        float bh = __half2float(__float2half_rn(b));
        g_X2h[i] = pack2(a, b);
        g_X8[i]  = pack_e4m3(a, b);
        g_X8l[i] = pack_e4m3((a - ah) * CS, (b - bh) * CS);
    }
}

// psi[j][n][m] -> scaled (x2^5), transposed, split into fp16-hi + fp8 + fp8-lo
__global__ void transpose_pack_psi(const float* __restrict__ psi) {
    __shared__ float sm[32][33];
    const int j = blockIdx.z;
    const int m0 = blockIdx.x * 32, n0 = blockIdx.y * 32;
    const int tid = threadIdx.x;
    const float* P = psi + (size_t)j * NN * NN;
    #pragma unroll
    for (int it = 0; it < 4; it++) {
        int idx = it * 256 + tid;
        int nl = idx >> 5, ml = idx & 31;
        sm[nl][ml] = P[(size_t)(n0 + nl) * NN + m0 + ml];
    }
    __syncthreads();
    const size_t obase = (size_t)j * NN * NW2 + (size_t)(n0 >> 1);
    #pragma unroll
    for (int it = 0; it < 2; it++) {
        int flat = it * 256 + tid;
        int ml = flat >> 4, n2l = flat & 15;
        float a = sm[2 * n2l][ml] * PS, b = sm[2 * n2l + 1][ml] * PS;
        float ah = __half2float(__float2half_rn(a));
        float bh = __half2float(__float2half_rn(b));
        size_t o = obase + (size_t)(m0 + ml) * NW2 + n2l;
        g_P2h[o] = pack2(a, b);
        g_P8[o]  = pack_e4m3(a, b);
        g_P8l[o] = pack_e4m3((a - ah) * CS, (b - bh) * CS);
    }
}

// ---------------- fused mixed fp16/fp8 tensor GEMM ----------------
// Tile 128x64, BK=32, 256 thr, 8 warps (4M x 2N). NI=4.
// fp16 planes: 80 B/row stride; fp8 planes: 48 B/row stride (both LDSM conflict-free).
#define OFF_AH  0
#define OFF_BH  10240
#define OFF_A8  15360
#define OFF_A8L 21504
#define OFF_B8  27648
#define OFF_B8L 30720
#define STB     33792
#define NKC     64
#define SMEM_BYTES (2*STB)       // 67584

template <int LAYER>
__global__ __launch_bounds__(256, 2)
void gemm_mix(const float* __restrict__ lp, float* __restrict__ phi) {
    extern __shared__ __align__(1024) char smc[];
    const uint32_t sb = smem_u32(smc);
    const int tid = threadIdx.x;
    const int lane = tid & 31, w = tid >> 5;
    const int wm = w & 3, wn = w >> 2;
    const int g = lane >> 2, t = lane & 3;
    const int j  = blockIdx.z;
    const int n0 = blockIdx.x * 64, m0 = blockIdx.y * 128;

    const uint32_t* s16A = ((LAYER == 1) ? g_X2h : g_S2h) + (size_t)m0 * NW2;
    const uint32_t* s16B = g_P2h + (size_t)j * NN * NW2 + (size_t)n0 * NW2;
    const uint16_t* s8A  = ((LAYER == 1) ? g_X8  : g_S8)  + (size_t)m0 * NH2;
    const uint16_t* s8Al = ((LAYER == 1) ? g_X8l : g_S8l) + (size_t)m0 * NH2;
    const uint16_t* s8B  = g_P8  + (size_t)j * NN * NH2 + (size_t)n0 * NH2;
    const uint16_t* s8Bl = g_P8l + (size_t)j * NN * NH2 + (size_t)n0 * NH2;

    // ldmatrix lane-address offsets
    const int lrow = lane & 7, lm = lane >> 3;
    uint32_t aoff[2], a8off[2];
    #pragma unroll
    for (int mi = 0; mi < 2; mi++) {
        int r = wm * 32 + mi * 16 + (lm & 1) * 8 + lrow;
        aoff[mi]  = (uint32_t)(r * 80 + (lm >> 1) * 16);
        a8off[mi] = (uint32_t)(r * 48 + (lm >> 1) * 16);
    }
    const uint32_t boff  = (uint32_t)((wn * 32 + (lm >> 1) * 8 + lrow) * 80 + (lm & 1) * 16);
    const uint32_t b8off = (uint32_t)((wn * 32 + (lm >> 1) * 8 + lrow) * 48 + (lm & 1) * 16);

    auto copy_stage = [&](int buf, int kc) {
        uint32_t st = sb + (uint32_t)buf * STB;
        // Ah: 128 rows x 4 chunks
        #pragma unroll
        for (int i = 0; i < 2; i++) {
            int cid = i * 256 + tid, row = cid >> 2, cc = cid & 3;
            cp16(st + OFF_AH + row * 80 + cc * 16, s16A + (size_t)row * NW2 + kc * 16 + cc * 4);
        }
        // Bh: 64 rows x 4 chunks
        { int row = tid >> 2, cc = tid & 3;
          cp16(st + OFF_BH + row * 80 + cc * 16, s16B + (size_t)row * NW2 + kc * 16 + cc * 4); }
        // A8 / A8l: 128 rows x 2 chunks each
        { int row = tid >> 1, cc = tid & 1;
          cp16(st + OFF_A8  + row * 48 + cc * 16, s8A  + (size_t)row * NH2 + kc * 16 + cc * 8);
          cp16(st + OFF_A8L + row * 48 + cc * 16, s8Al + (size_t)row * NH2 + kc * 16 + cc * 8); }
        // B8 (tid<128) / B8l (tid>=128): 64 rows x 2 chunks
        if (tid < 128) {
            int row = tid >> 1, cc = tid & 1;
            cp16(st + OFF_B8 + row * 48 + cc * 16, s8B + (size_t)row * NH2 + kc * 16 + cc * 8);
        } else {
            int t2 = tid - 128, row = t2 >> 1, cc = t2 & 1;
            cp16(st + OFF_B8L + row * 48 + cc * 16, s8Bl + (size_t)row * NH2 + kc * 16 + cc * 8);
        }
        asm volatile("cp.async.commit_group;\n");
    };

    float cm[2][4][4] = {};    // main (fp16) accum, value = C * 2^5
    float cx[2][4][4] = {};    // cross (fp8) accum, value = C_cross * 2^17

    copy_stage(0, 0);
    for (int kt = 0; kt < NKC; kt++) {
        const int buf = kt & 1;
        if (kt + 1 < NKC) {
            copy_stage(buf ^ 1, kt + 1);
            asm volatile("cp.async.wait_group 1;\n");
        } else {
            asm volatile("cp.async.wait_group 0;\n");
        }
        __syncthreads();

        const uint32_t st = sb + (uint32_t)buf * STB;

        // fp16 main term (2 k-steps of 16)
        #pragma unroll
        for (int kk = 0; kk < 2; kk++) {
            const uint32_t kb = kk * 32;
            uint32_t ah[2][4], bhf[2][4];
            LDSM4(ah[0], st + OFF_AH + aoff[0] + kb);
            LDSM4(ah[1], st + OFF_AH + aoff[1] + kb);
            LDSM4(bhf[0], st + OFF_BH + boff + kb);
            LDSM4(bhf[1], st + OFF_BH + boff + 1280 + kb);
            #pragma unroll
            for (int ni = 0; ni < 4; ni++) {
                uint32_t b0 = bhf[ni >> 1][(ni & 1) * 2], b1 = bhf[ni >> 1][(ni & 1) * 2 + 1];
                MMA_F16(cm[0][ni], ah[0], b0, b1);
                MMA_F16(cm[1][ni], ah[1], b0, b1);
            }
        }
        // fp8 cross terms (single k32 step covers the chunk)
        {
            uint32_t a8[2][4], a8l[2][4], b8[2][4], b8l[2][4];
            LDSM4(a8[0],  st + OFF_A8  + a8off[0]);
            LDSM4(a8[1],  st + OFF_A8  + a8off[1]);
            LDSM4(a8l[0], st + OFF_A8L + a8off[0]);
            LDSM4(a8l[1], st + OFF_A8L + a8off[1]);
            LDSM4(b8[0],  st + OFF_B8  + b8off);
            LDSM4(b8[1],  st + OFF_B8  + b8off + 768);
            LDSM4(b8l[0], st + OFF_B8L + b8off);
            LDSM4(b8l[1], st + OFF_B8L + b8off + 768);
            #pragma unroll
            for (int ni = 0; ni < 4; ni++) {
                uint32_t b0 = b8[ni >> 1][(ni & 1) * 2], b1 = b8[ni >> 1][(ni & 1) * 2 + 1];
                MMA_E4M3(cx[0][ni], a8l[0], b0, b1);   // Al_s * B
                MMA_E4M3(cx[1][ni], a8l[1], b0, b1);
            }
            #pragma unroll
            for (int ni = 0; ni < 4; ni++) {
                uint32_t b0 = b8l[ni >> 1][(ni & 1) * 2], b1 = b8l[ni >> 1][(ni & 1) * 2 + 1];
                MMA_E4M3(cx[0][ni], a8[0], b0, b1);    // A * Bl_s
                MMA_E4M3(cx[1][ni], a8[1], b0, b1);
            }
        }
        __syncthreads();
    }

    // Epilogue: C = cm*2^-5 + cx*2^-17; abs + lowpass; layer-1 repacks S1.
    float p[2][2] = {};
    #pragma unroll
    for (int mi = 0; mi < 2; mi++) {
        #pragma unroll
        for (int ni = 0; ni < 4; ni++) {
            const int m = n0 + wn * 32 + ni * 8 + 2 * t;
            float v0 = fabsf(cm[mi][ni][0] * S_MAIN + cx[mi][ni][0] * S_CORR);
            float v1 = fabsf(cm[mi][ni][1] * S_MAIN + cx[mi][ni][1] * S_CORR);
            float v2 = fabsf(cm[mi][ni][2] * S_MAIN + cx[mi][ni][2] * S_CORR);
            float v3 = fabsf(cm[mi][ni][3] * S_MAIN + cx[mi][ni][3] * S_CORR);
            float l0 = __ldg(&lp[m]), l1 = __ldg(&lp[m + 1]);
            p[mi][0] += v0 * l0 + v1 * l1;
            p[mi][1] += v2 * l0 + v3 * l1;
            if (LAYER == 1) {
                const int r0 = m0 + wm * 32 + mi * 16 + g;
                const int r1 = r0 + 8;
                int s0 = (((r0 >> 4) * JS + j) << 4) + (r0 & 15);
                int s1 = (((r1 >> 4) * JS + j) << 4) + (r1 & 15);
                float h0 = __half2float(__float2half_rn(v0));
                float h1 = __half2float(__float2half_rn(v1));
                float h2 = __half2float(__float2half_rn(v2));
                float h3 = __half2float(__float2half_rn(v3));
                size_t w0 = (size_t)s0 * NW2 + (m >> 1);
                size_t w1 = (size_t)s1 * NW2 + (m >> 1);
                g_S2h[w0] = pack2(v0, v1);
                g_S2h[w1] = pack2(v2, v3);
                g_S8[w0]  = pack_e4m3(v0, v1);
                g_S8[w1]  = pack_e4m3(v2, v3);
                g_S8l[w0] = pack_e4m3((v0 - h0) * CS, (v1 - h1) * CS);
                g_S8l[w1] = pack_e4m3((v2 - h2) * CS, (v3 - h3) * CS);
            }
        }
    }
    #pragma unroll
    for (int mi = 0; mi < 2; mi++) {
        #pragma unroll
        for (int s = 0; s < 2; s++) {
            float v = p[mi][s];
            v += __shfl_xor_sync(0xffffffffu, v, 1);
            v += __shfl_xor_sync(0xffffffffu, v, 2);
            if (t == 0) {
                const int r = m0 + wm * 32 + mi * 16 + g + s * 8;
                int b, f, col;
                if (LAYER == 1) { b = r >> 4; f = r & 15; col = 1 + j; }
                else { b = r >> 6; int j1 = (r >> 4) & 3; f = r & 15; col = 5 + j1 * 4 + j; }
                atomicAdd(&phi[(b * FF + f) * NCOLS + col], v);
            }
        }
    }
}

// ---------------- launch ----------------
extern "C" void kernel_launch(void* const* d_in, const int* in_sizes, int n_in,
                              void* d_out, int out_size) {
    const float* x   = (const float*)d_in[0];   // (8,16,2048)
    const float* psi = (const float*)d_in[1];   // (4,2048,2048)
    const float* lp  = (const float*)d_in[2];   // (2048,)
    float* out = (float*)d_out;                 // (8,16,21)
    (void)in_sizes; (void)n_in; (void)out_size;

    cudaFuncSetAttribute(gemm_mix<1>, cudaFuncAttributeMaxDynamicSharedMemorySize, SMEM_BYTES);
    cudaFuncSetAttribute(gemm_mix<2>, cudaFuncAttributeMaxDynamicSharedMemorySize, SMEM_BYTES);

    zero_phi_kernel<<<(OUT_ELEMS + 255) / 256, 256>>>(out);
    phi0_kernel<<<BB * FF, 256>>>(x, lp, out);
    split_pack_x<<<(BB * FF * NW2 + 255) / 256, 256>>>(x);
    transpose_pack_psi<<<dim3(NN / 32, NN / 32, JS), 256>>>(psi);
    // layer 1: TN=64 -> 32 N-tiles x 1 M-tile x 4 j
    gemm_mix<1><<<dim3(32, 1, 4), 256, SMEM_BYTES>>>(lp, out);
    // layer 2: TN=64 -> 32 N-tiles x 4 M-tiles x 4 j
    gemm_mix<2><<<dim3(32, 4, 4), 256, SMEM_BYTES>>>(lp, out);
}

// round 10
// speedup vs baseline: 1.5240x; 1.5240x over previous
#include <cuda_runtime.h>
#include <cuda_fp16.h>
#include <math.h>
#include <stdint.h>

// Problem constants
#define BB 8
#define FF 16
#define NN 2048
#define JS 4
#define NCOLS 21
#define OUT_ELEMS (BB*FF*NCOLS)
#define NW2 1024                 // packed fp16-pair words per row

// ---------------- packed hi/lo scratch (uint32 = 2 x fp16) ----------------
__device__ __align__(256) uint32_t g_X2h[BB*FF*NW2], g_X2l[BB*FF*NW2];
__device__ __align__(256) uint32_t g_P2h[(size_t)JS*NN*NW2];
__device__ __align__(256) uint32_t g_P2l[(size_t)JS*NN*NW2];
__device__ __align__(256) uint32_t g_S2h[(size_t)BB*JS*FF*NW2];
__device__ __align__(256) uint32_t g_S2l[(size_t)BB*JS*FF*NW2];

// ---------------- helpers ----------------
__device__ __forceinline__ uint32_t smem_u32(const void* p) {
    uint32_t a;
    asm("{ .reg .u64 t; cvta.to.shared.u64 t, %1; cvt.u32.u64 %0, t; }" : "=r"(a) : "l"(p));
    return a;
}
__device__ __forceinline__ void cp16(uint32_t s, const void* g) {
    asm volatile("cp.async.cg.shared.global [%0], [%1], 16;\n" :: "r"(s), "l"(g));
}
__device__ __forceinline__ uint32_t pack2(float a, float b) {
    __half2 h = __floats2half2_rn(a, b);
    return *reinterpret_cast<uint32_t*>(&h);
}
#define MMA_F16(C, A, B0, B1)                                                 \
    asm volatile(                                                             \
        "mma.sync.aligned.m16n8k16.row.col.f32.f16.f16.f32 "                  \
        "{%0,%1,%2,%3}, {%4,%5,%6,%7}, {%8,%9}, {%0,%1,%2,%3};\n"             \
        : "+f"((C)[0]), "+f"((C)[1]), "+f"((C)[2]), "+f"((C)[3])              \
        : "r"((A)[0]), "r"((A)[1]), "r"((A)[2]), "r"((A)[3]), "r"(B0), "r"(B1))
#define LDSM4(R, addr)                                                        \
    asm volatile("ldmatrix.sync.aligned.m8n8.x4.shared.b16 {%0,%1,%2,%3}, [%4];" \
        : "=r"((R)[0]), "=r"((R)[1]), "=r"((R)[2]), "=r"((R)[3]) : "r"(addr))

// ---------------- fused prep: phi0 + phi-zero + x hi/lo split ----------------
// 128 blocks (one per row r=b*16+f) x 256 threads. Single pass over x.
__global__ void prep_kernel(const float* __restrict__ x, const float* __restrict__ lp,
                            float* __restrict__ out) {
    const int r = blockIdx.x, tid = threadIdx.x;
    const float2* x2 = (const float2*)(x) + (size_t)r * NW2;
    const float2* lp2 = (const float2*)lp;
    float s = 0.0f;
    #pragma unroll
    for (int it = 0; it < 4; it++) {
        int wd = it * 256 + tid;
        float2 v = x2[wd];
        float2 l = lp2[wd];
        s += v.x * l.x + v.y * l.y;
        float ah = __half2float(__float2half_rn(v.x));
        float bh = __half2float(__float2half_rn(v.y));
        g_X2h[r * NW2 + wd] = pack2(v.x, v.y);
        g_X2l[r * NW2 + wd] = pack2(v.x - ah, v.y - bh);
    }
    if (tid >= 1 && tid < NCOLS) out[r * NCOLS + tid] = 0.0f;   // zero phi cols 1..20
    __shared__ float red[8];
    #pragma unroll
    for (int o = 16; o; o >>= 1) s += __shfl_xor_sync(0xffffffffu, s, o);
    if ((tid & 31) == 0) red[tid >> 5] = s;
    __syncthreads();
    if (tid < 8) {
        s = red[tid];
        #pragma unroll
        for (int o = 4; o; o >>= 1) s += __shfl_xor_sync(0xffu, s, o);
        if (tid == 0) out[r * NCOLS + 0] = s;                   // exact fp32 phi0
    }
}

// ---------------- psi transpose+split, wide-IO edition ----------------
// psi[j][n][m] -> P2{h,l}[j][m][n2].  32n x 32m tiles; float4 loads; uint2 stores.
// Write-phase smem reads sm[4p+q][ml]: bank = (4p+q+ml)%32, all 32 lanes distinct.
__global__ void transpose_pack_psi(const float* __restrict__ psi) {
    __shared__ float sm[32][33];
    const int j = blockIdx.z;
    const int m0 = blockIdx.x * 32, n0 = blockIdx.y * 32;
    const int tid = threadIdx.x;
    const float* P = psi + (size_t)j * NN * NN;

    // load 32 n-rows x 32 m-cols as float4 (1 per thread)
    {
        int nl = tid >> 3, c4 = tid & 7;
        float4 v = *(const float4*)&P[(size_t)(n0 + nl) * NN + m0 + c4 * 4];
        sm[nl][c4 * 4 + 0] = v.x;
        sm[nl][c4 * 4 + 1] = v.y;
        sm[nl][c4 * 4 + 2] = v.z;
        sm[nl][c4 * 4 + 3] = v.w;
    }
    __syncthreads();

    // each thread packs 4 n-values (2 words) for one m-row -> uint2 stores
    {
        int ml = tid >> 3, p = tid & 7;
        float a0 = sm[4 * p + 0][ml], a1 = sm[4 * p + 1][ml];
        float a2 = sm[4 * p + 2][ml], a3 = sm[4 * p + 3][ml];
        float h0 = __half2float(__float2half_rn(a0));
        float h1 = __half2float(__float2half_rn(a1));
        float h2 = __half2float(__float2half_rn(a2));
        float h3 = __half2float(__float2half_rn(a3));
        size_t o = (size_t)j * NN * NW2 + (size_t)(m0 + ml) * NW2 + (n0 >> 1) + 2 * p;
        uint2 hw = make_uint2(pack2(a0, a1), pack2(a2, a3));
        uint2 lw = make_uint2(pack2(a0 - h0, a1 - h1), pack2(a2 - h2, a3 - h3));
        *(uint2*)&g_P2h[o] = hw;
        *(uint2*)&g_P2l[o] = lw;
    }
}

// ---------------- fused fp16 3-term tensor GEMM (R8, unchanged) -------------
// Tile 128 x TN (TN=16*NI), BK=32, 256 thr, 8 warps (4M x 2N).
// smem planes (Ah,Al,Bh,Bl), 80 B/row (stride-20 words): ldmatrix conflict-free.
template <int LAYER, int NI>
__global__ __launch_bounds__(256, 2)
void gemm_f16(const float* __restrict__ lp, float* __restrict__ phi) {
    constexpr int TN  = NI * 16;
    constexpr int APL = 128 * 80;            // A plane bytes
    constexpr int BPL = TN * 80;             // B plane bytes
    constexpr int STB = 2 * APL + 2 * BPL;   // stage bytes
    constexpr int NKC = 64;                  // 2048/32 k-chunks

    extern __shared__ __align__(1024) char smc[];
    const uint32_t sb = smem_u32(smc);
    const int tid = threadIdx.x;
    const int lane = tid & 31, w = tid >> 5;
    const int wm = w & 3, wn = w >> 2;
    const int g = lane >> 2, t = lane & 3;
    const int j  = blockIdx.z;
    const int n0 = blockIdx.x * TN, m0 = blockIdx.y * 128;

    const uint32_t* srcs[4] = {
        ((LAYER == 1) ? g_X2h : g_S2h) + (size_t)m0 * NW2,
        ((LAYER == 1) ? g_X2l : g_S2l) + (size_t)m0 * NW2,
        g_P2h + (size_t)j * NN * NW2 + (size_t)n0 * NW2,
        g_P2l + (size_t)j * NN * NW2 + (size_t)n0 * NW2 };

    const int lrow = lane & 7, lm = lane >> 3;
    uint32_t aoff[2];
    #pragma unroll
    for (int mi = 0; mi < 2; mi++)
        aoff[mi] = (uint32_t)((wm * 32 + mi * 16 + (lm & 1) * 8 + lrow) * 80
                              + (lm >> 1) * 16);
    const uint32_t boff = (uint32_t)((wn * NI * 8 + (lm >> 1) * 8 + lrow) * 80
                                     + (lm & 1) * 16);

    auto copy_stage = [&](int buf, int kc) {
        uint32_t st = sb + buf * STB;
        #pragma unroll
        for (int pl = 0; pl < 2; pl++) {
            uint32_t pb = st + pl * APL;
            const uint32_t* s = srcs[pl] + kc * 16;
            #pragma unroll
            for (int i = 0; i < 2; i++) {
                int cid = i * 256 + tid, row = cid >> 2, cc = cid & 3;
                cp16(pb + row * 80 + cc * 16, s + (size_t)row * NW2 + cc * 4);
            }
        }
        constexpr int BPC = (TN * 4) / 256;
        #pragma unroll
        for (int pl = 0; pl < 2; pl++) {
            uint32_t pb = st + 2 * APL + pl * BPL;
            const uint32_t* s = srcs[2 + pl] + kc * 16;
            #pragma unroll
            for (int i = 0; i < BPC; i++) {
                int cid = i * 256 + tid, row = cid >> 2, cc = cid & 3;
                cp16(pb + row * 80 + cc * 16, s + (size_t)row * NW2 + cc * 4);
            }
        }
        asm volatile("cp.async.commit_group;\n");
    };

    float c[2][NI][4] = {};

    copy_stage(0, 0);
    for (int kt = 0; kt < NKC; kt++) {
        const int buf = kt & 1;
        if (kt + 1 < NKC) {
            copy_stage(buf ^ 1, kt + 1);
            asm volatile("cp.async.wait_group 1;\n");
        } else {
            asm volatile("cp.async.wait_group 0;\n");
        }
        __syncthreads();

        const uint32_t st = sb + buf * STB;
        #pragma unroll
        for (int kk = 0; kk < 2; kk++) {
            const uint32_t kb = kk * 32;
            uint32_t ah[2][4], al[2][4], bh[NI / 2][4];
            LDSM4(ah[0], st + aoff[0] + kb);
            LDSM4(ah[1], st + aoff[1] + kb);
            LDSM4(al[0], st + APL + aoff[0] + kb);
            LDSM4(al[1], st + APL + aoff[1] + kb);
            #pragma unroll
            for (int q = 0; q < NI / 2; q++)
                LDSM4(bh[q], st + 2 * APL + boff + q * 1280 + kb);

            #pragma unroll
            for (int ni = 0; ni < NI; ni++) {    // term 0: Al x Bh
                uint32_t b0 = bh[ni >> 1][(ni & 1) * 2], b1 = bh[ni >> 1][(ni & 1) * 2 + 1];
                MMA_F16(c[0][ni], al[0], b0, b1);
                MMA_F16(c[1][ni], al[1], b0, b1);
            }
            #pragma unroll
            for (int q = 0; q < NI / 2; q++) {   // term 1: Ah x Bl (streamed)
                uint32_t bl[4];
                LDSM4(bl, st + 2 * APL + BPL + boff + q * 1280 + kb);
                #pragma unroll
                for (int s = 0; s < 2; s++) {
                    MMA_F16(c[0][q * 2 + s], ah[0], bl[s * 2], bl[s * 2 + 1]);
                    MMA_F16(c[1][q * 2 + s], ah[1], bl[s * 2], bl[s * 2 + 1]);
                }
            }
            #pragma unroll
            for (int ni = 0; ni < NI; ni++) {    // term 2: Ah x Bh
                uint32_t b0 = bh[ni >> 1][(ni & 1) * 2], b1 = bh[ni >> 1][(ni & 1) * 2 + 1];
                MMA_F16(c[0][ni], ah[0], b0, b1);
                MMA_F16(c[1][ni], ah[1], b0, b1);
            }
        }
        __syncthreads();
    }

    // Epilogue: abs + lowpass partials; layer-1 packs S1 hi/lo.
    float p[2][2] = {};
    #pragma unroll
    for (int mi = 0; mi < 2; mi++) {
        #pragma unroll
        for (int ni = 0; ni < NI; ni++) {
            const int m = n0 + wn * NI * 8 + ni * 8 + 2 * t;
            float v0 = fabsf(c[mi][ni][0]), v1 = fabsf(c[mi][ni][1]);
            float v2 = fabsf(c[mi][ni][2]), v3 = fabsf(c[mi][ni][3]);
            float l0 = __ldg(&lp[m]), l1 = __ldg(&lp[m + 1]);
            p[mi][0] += v0 * l0 + v1 * l1;
            p[mi][1] += v2 * l0 + v3 * l1;
            if (LAYER == 1) {
                const int r0 = m0 + wm * 32 + mi * 16 + g;
                const int r1 = r0 + 8;
                int s0 = (((r0 >> 4) * JS + j) << 4) + (r0 & 15);
                int s1 = (((r1 >> 4) * JS + j) << 4) + (r1 & 15);
                float h0 = __half2float(__float2half_rn(v0));
                float h1 = __half2float(__float2half_rn(v1));
                float h2 = __half2float(__float2half_rn(v2));
                float h3 = __half2float(__float2half_rn(v3));
                g_S2h[(size_t)s0 * NW2 + (m >> 1)] = pack2(v0, v1);
                g_S2l[(size_t)s0 * NW2 + (m >> 1)] = pack2(v0 - h0, v1 - h1);
                g_S2h[(size_t)s1 * NW2 + (m >> 1)] = pack2(v2, v3);
                g_S2l[(size_t)s1 * NW2 + (m >> 1)] = pack2(v2 - h2, v3 - h3);
            }
        }
    }
    #pragma unroll
    for (int mi = 0; mi < 2; mi++) {
        #pragma unroll
        for (int s = 0; s < 2; s++) {
            float v = p[mi][s];
            v += __shfl_xor_sync(0xffffffffu, v, 1);
            v += __shfl_xor_sync(0xffffffffu, v, 2);
            if (t == 0) {
                const int r = m0 + wm * 32 + mi * 16 + g + s * 8;
                int b, f, col;
                if (LAYER == 1) { b = r >> 4; f = r & 15; col = 1 + j; }
                else { b = r >> 6; int j1 = (r >> 4) & 3; f = r & 15; col = 5 + j1 * 4 + j; }
                atomicAdd(&phi[(b * FF + f) * NCOLS + col], v);
            }
        }
    }
}

// ---------------- launch ----------------
extern "C" void kernel_launch(void* const* d_in, const int* in_sizes, int n_in,
                              void* d_out, int out_size) {
    const float* x   = (const float*)d_in[0];   // (8,16,2048)
    const float* psi = (const float*)d_in[1];   // (4,2048,2048)
    const float* lp  = (const float*)d_in[2];   // (2048,)
    float* out = (float*)d_out;                 // (8,16,21)
    (void)in_sizes; (void)n_in; (void)out_size;

    constexpr int SM1 = 2 * (2 * 128 * 80 + 2 * 64 * 80);    // 61440 (NI=4)
    constexpr int SM2 = 2 * (2 * 128 * 80 + 2 * 128 * 80);   // 81920 (NI=8)
    cudaFuncSetAttribute(gemm_f16<1, 4>, cudaFuncAttributeMaxDynamicSharedMemorySize, SM1);
    cudaFuncSetAttribute(gemm_f16<2, 8>, cudaFuncAttributeMaxDynamicSharedMemorySize, SM2);

    prep_kernel<<<BB * FF, 256>>>(x, lp, out);               // phi0 + zero + x split
    transpose_pack_psi<<<dim3(64, 64, JS), 256>>>(psi);
    gemm_f16<1, 4><<<dim3(32, 1, 4), 256, SM1>>>(lp, out);   // layer 1
    gemm_f16<2, 8><<<dim3(16, 4, 4), 256, SM2>>>(lp, out);   // layer 2
}